// round 8
// baseline (speedup 1.0000x reference)
#include <cuda_runtime.h>

#define N_ROWS 32768
#define D_DIM  256
#define K_CODES 2048

#define BM 128   // rows per block
#define BN 128   // codes per tile
#define BK 16    // D chunk
#define TM 8
#define TN 8
#define XLD  132 // sC row stride (floats): 16B-aligned, bank-rotating
#define X2LD 264 // sX2 (duplicated) row stride (floats): 16B-aligned

#define NBLK (N_ROWS / BM)   // 256

typedef unsigned long long u64;

__device__ float g_xnorm[N_ROWS];
__device__ float g_cnorm[K_CODES];
__device__ float g_partial[NBLK];

// packed fp32x2 FMA (Blackwell FFMA2) — per-lane IEEE fp32 FMA, so the
// accumulation is bit-identical to two scalar fmaf in the same k-order.
__device__ __forceinline__ u64 ffma2(u64 a, u64 b, u64 c) {
    u64 d;
    asm("fma.rn.f32x2 %0, %1, %2, %3;" : "=l"(d) : "l"(a), "l"(b), "l"(c));
    return d;
}
__device__ __forceinline__ float f2lo(u64 v) { return __uint_as_float((unsigned)v); }
__device__ __forceinline__ float f2hi(u64 v) { return __uint_as_float((unsigned)(v >> 32)); }

// ---------------------------------------------------------------------------
// Bit-exact replica of XLA:GPU row reduction for a 256-wide f32 row:
// 128 threads x vec2, intra-warp shfl tree, cross-warp (w0+w2)+(w1+w3).
// ---------------------------------------------------------------------------
__device__ __forceinline__ float xla_row_sumsq(const float* __restrict__ row,
                                               int lane) {
    float s[4];
#pragma unroll
    for (int g = 0; g < 4; g++) {
        float x0 = row[64 * g + 2 * lane];
        float x1 = row[64 * g + 2 * lane + 1];
        s[g] = __fadd_rn(__fmul_rn(x0, x0), __fmul_rn(x1, x1));
    }
#pragma unroll
    for (int off = 16; off > 0; off >>= 1) {
#pragma unroll
        for (int g = 0; g < 4; g++)
            s[g] = __fadd_rn(s[g], __shfl_down_sync(0xffffffffu, s[g], off));
    }
    return __fadd_rn(__fadd_rn(s[0], s[2]), __fadd_rn(s[1], s[3]));
}

__global__ void norms_kernel(const float* __restrict__ x,
                             const float* __restrict__ cb) {
    int warp = (blockIdx.x * blockDim.x + threadIdx.x) >> 5;
    int lane = threadIdx.x & 31;
    if (warp < N_ROWS) {
        float a = xla_row_sumsq(x + (size_t)warp * D_DIM, lane);
        if (lane == 0) g_xnorm[warp] = a;
    } else if (warp < N_ROWS + K_CODES) {
        int j = warp - N_ROWS;
        float b = xla_row_sumsq(cb + (size_t)j * D_DIM, lane);
        if (lane == 0) g_cnorm[j] = b;
    }
}

// ---------------------------------------------------------------------------
// Fused FFMA2 GEMM + quantized-argmin + gather + loss partial.
// Block = 128 rows x all 2048 codes (16 tiles of 128).
//   X tile stored DUPLICATED in smem: each element as (v,v) so a 128-bit LDS
//   yields two SIMD-2 broadcast operands (address = f(ty) only -> broadcast).
//   C tile stored transposed as before: adjacent codes form natural pairs.
// Score chain is the frozen bit-exact reference replica:
//   d = fl( fl(xnorm + cnorm) - fl(2 * dot) ), ties -> lowest index.
// ---------------------------------------------------------------------------
__global__ __launch_bounds__(256, 2)
void vq_main_kernel(const float* __restrict__ x, const float* __restrict__ cb,
                    float* __restrict__ out) {
    __shared__ float sX2[BK * X2LD];  // [k][2*row] duplicated X
    __shared__ float sC[BK * XLD];    // [k][code]  transposed C
    __shared__ float sCN[BN];
    __shared__ int   sWidx[BM];

    // aliases for post-GEMM reductions (tiles dead by then)
    float* sred = sX2;               // needs 16*128 floats <= 16*264
    int*   ired = (int*)sC;          // needs 16*128 ints   <= 16*132

    const int tid = threadIdx.x;
    const int tx  = tid & 15;
    const int ty  = tid >> 4;
    const int rowBase = blockIdx.x * BM;

    float ar[TM];
#pragma unroll
    for (int r = 0; r < TM; r++) ar[r] = g_xnorm[rowBase + ty * TM + r];

    float bs[TM];
    int   bi[TM];
#pragma unroll
    for (int r = 0; r < TM; r++) { bs[r] = 3.4e38f; bi[r] = 0; }

    for (int t = 0; t < K_CODES / BN; t++) {
        __syncthreads();                       // prior tile's sCN reads done
        if (tid < BN) sCN[tid] = g_cnorm[t * BN + tid];

        u64 acc2[TM][TN / 2];
#pragma unroll
        for (int r = 0; r < TM; r++)
#pragma unroll
            for (int c = 0; c < TN / 2; c++) acc2[r][c] = 0ull;

        const float* cbase = cb + (size_t)(t * BN) * D_DIM;

        for (int dk = 0; dk < D_DIM; dk += BK) {
            __syncthreads();                   // prior compute done reading tiles
            // load + transpose: 512 float4 per tensor, 2 per thread
#pragma unroll
            for (int l = 0; l < 2; l++) {
                int i   = tid + l * 256;       // 0..511
                int row = i >> 2;              // 0..127
                int j   = (i & 3) << 2;        // 0,4,8,12
                float4 v = *(const float4*)(x + (size_t)(rowBase + row) * D_DIM + dk + j);
                *(float2*)&sX2[(j + 0) * X2LD + 2 * row] = make_float2(v.x, v.x);
                *(float2*)&sX2[(j + 1) * X2LD + 2 * row] = make_float2(v.y, v.y);
                *(float2*)&sX2[(j + 2) * X2LD + 2 * row] = make_float2(v.z, v.z);
                *(float2*)&sX2[(j + 3) * X2LD + 2 * row] = make_float2(v.w, v.w);
                float4 w = *(const float4*)(cbase + (size_t)row * D_DIM + dk + j);
                sC[(j + 0) * XLD + row] = w.x;
                sC[(j + 1) * XLD + row] = w.y;
                sC[(j + 2) * XLD + row] = w.z;
                sC[(j + 3) * XLD + row] = w.w;
            }
            __syncthreads();

#pragma unroll
            for (int k = 0; k < BK; k++) {
                // duplicated row pairs: (row, row) per u64, rows ty*8 + 0..7
                const ulonglong2 a0 = *(const ulonglong2*)&sX2[k * X2LD + 16 * ty];
                const ulonglong2 a1 = *(const ulonglong2*)&sX2[k * X2LD + 16 * ty + 4];
                const ulonglong2 a2 = *(const ulonglong2*)&sX2[k * X2LD + 16 * ty + 8];
                const ulonglong2 a3 = *(const ulonglong2*)&sX2[k * X2LD + 16 * ty + 12];
                // natural code pairs: codes tx*8 + (0,1),(2,3),(4,5),(6,7)
                const ulonglong2 b0 = *(const ulonglong2*)&sC[k * XLD + tx * TN];
                const ulonglong2 b1 = *(const ulonglong2*)&sC[k * XLD + tx * TN + 4];
                const u64 xr2[TM] = {a0.x, a0.y, a1.x, a1.y, a2.x, a2.y, a3.x, a3.y};
                const u64 cc2[TN / 2] = {b0.x, b0.y, b1.x, b1.y};
#pragma unroll
                for (int r = 0; r < TM; r++)
#pragma unroll
                    for (int c = 0; c < TN / 2; c++)
                        acc2[r][c] = ffma2(xr2[r], cc2[c], acc2[r][c]);
            }
        }

        // quantized-argmin epilogue for this code tile. Exact reference
        // rounding chain; strict '<' + ascending code order keeps the
        // first (lowest-index) minimum, matching jnp.argmin.
#pragma unroll
        for (int r = 0; r < TM; r++) {
#pragma unroll
            for (int c2 = 0; c2 < TN / 2; c2++) {
                int ce = tx * TN + 2 * c2;
                float de = f2lo(acc2[r][c2]);
                float doo = f2hi(acc2[r][c2]);
                float Te = __fadd_rn(ar[r], sCN[ce]);
                float se = __fsub_rn(Te, __fmul_rn(2.0f, de));
                if (se < bs[r]) { bs[r] = se; bi[r] = t * BN + ce; }
                float To = __fadd_rn(ar[r], sCN[ce + 1]);
                float so = __fsub_rn(To, __fmul_rn(2.0f, doo));
                if (so < bs[r]) { bs[r] = so; bi[r] = t * BN + ce + 1; }
            }
        }
    }

    // cross-thread argmin reduction: 16 tx-threads share each row
    __syncthreads();
#pragma unroll
    for (int r = 0; r < TM; r++) {
        int srow = ty * TM + r;
        sred[tx * BM + srow] = bs[r];
        ired[tx * BM + srow] = bi[r];
    }
    __syncthreads();
    if (tid < BM) {
        float best = sred[tid];
        int   bidx = ired[tid];
#pragma unroll
        for (int p = 1; p < 16; p++) {
            float s = sred[p * BM + tid];
            int   id = ired[p * BM + tid];
            if (s < best || (s == best && id < bidx)) { best = s; bidx = id; }
        }
        sWidx[tid] = bidx;
    }
    __syncthreads();

    // gather winners, write x + (c - x) (reference's exact rounding), loss partial
    float lsum = 0.f;
    for (int i = tid; i < BM * (D_DIM / 4); i += 256) {
        int row = i >> 6;               // D_DIM/4 == 64
        int c4  = (i & 63) << 2;
        size_t goff = (size_t)(rowBase + row) * D_DIM + c4;
        float4 xv = *(const float4*)(x + goff);
        float4 cv = *(const float4*)(cb + (size_t)sWidx[row] * D_DIM + c4);
        float4 o;
        o.x = __fadd_rn(xv.x, __fsub_rn(cv.x, xv.x));
        o.y = __fadd_rn(xv.y, __fsub_rn(cv.y, xv.y));
        o.z = __fadd_rn(xv.z, __fsub_rn(cv.z, xv.z));
        o.w = __fadd_rn(xv.w, __fsub_rn(cv.w, xv.w));
        *(float4*)(out + goff) = o;
        float dx = __fsub_rn(xv.x, cv.x); lsum = fmaf(dx, dx, lsum);
        float dy = __fsub_rn(xv.y, cv.y); lsum = fmaf(dy, dy, lsum);
        float dz = __fsub_rn(xv.z, cv.z); lsum = fmaf(dz, dz, lsum);
        float dw = __fsub_rn(xv.w, cv.w); lsum = fmaf(dw, dw, lsum);
    }
    __syncthreads();
    sred[tid] = lsum;
    __syncthreads();
#pragma unroll
    for (int s = 128; s > 0; s >>= 1) {
        if (tid < s) sred[tid] += sred[tid + s];
        __syncthreads();
    }
    if (tid == 0) g_partial[blockIdx.x] = sred[0];
}

// ---------------------------------------------------------------------------
// Deterministic loss finalize. loss = 1.25 * mean((x-c)^2)
// (commit == embed bitwise in fp32, beta = 0.25).
// ---------------------------------------------------------------------------
__global__ void loss_kernel(float* __restrict__ out, int out_size) {
    __shared__ double sd[256];
    int tid = threadIdx.x;
    sd[tid] = (double)g_partial[tid];
    __syncthreads();
#pragma unroll
    for (int s = 128; s > 0; s >>= 1) {
        if (tid < s) sd[tid] += sd[tid + s];
        __syncthreads();
    }
    if (tid == 0) {
        double mean = sd[0] / (double)((size_t)N_ROWS * D_DIM);
        out[out_size - 1] = (float)(1.25 * mean);
    }
}

// ---------------------------------------------------------------------------
extern "C" void kernel_launch(void* const* d_in, const int* in_sizes, int n_in,
                              void* d_out, int out_size) {
    const float* x  = (const float*)d_in[0];   // [N, D]
    const float* cb = (const float*)d_in[1];   // [K, D]
    float* out = (float*)d_out;                // [N*D] quantized + [1] loss

    (void)in_sizes; (void)n_in;

    norms_kernel<<<(N_ROWS + K_CODES) / 8, 256>>>(x, cb);
    vq_main_kernel<<<NBLK, 256>>>(x, cb, out);
    loss_kernel<<<1, 256>>>(out, out_size);
}

// round 14
// speedup vs baseline: 1.1250x; 1.1250x over previous
#include <cuda_runtime.h>
#include <cstdint>

#define N_ROWS  32768
#define D_DIM   256
#define K_CODES 2048
#define K3      768                 // 3 tf32 segments of 256
#define BM      256                 // rows per CTA
#define BN      128                 // codes per pass tile
#define BK      32                  // k per chunk
#define NBLK    (N_ROWS / BM)       // 128
#define PASSES  (K_CODES / BN)      // 16
#define NCHUNK  (K3 / BK)           // 24
#define AST     36                  // smem A row stride (floats), bank-exact
#define BST     36
#define EPS_FLAG 1.2e-4f            // > 2 score-grid steps (2*3.05e-5) + margin
#define GBLK    256                 // gather kernel blocks (128 rows each)

typedef unsigned int u32;

// static device scratch (sanctioned workaround; no runtime allocs)
__device__ float XA[(size_t)N_ROWS * K3];     // [xhi | xhi | xlo]
__device__ float CB[(size_t)K_CODES * K3];    // [chi | clo | chi]
__device__ float g_xnorm[N_ROWS];
__device__ float g_cnorm[K_CODES];
__device__ float g_partial[GBLK];
__device__ int   g_widx[N_ROWS];
__device__ int   g_flaglist[N_ROWS];
__device__ int   g_flagcnt;

// ---------------- helpers (baseline PTX only; no sm_103a features) ---------
__device__ __forceinline__ u32 smem_u32(const void* p) {
    u32 a;
    asm("{ .reg .u64 t; cvta.to.shared.u64 t, %1; cvt.u32.u64 %0, t; }" : "=r"(a) : "l"(p));
    return a;
}
__device__ __forceinline__ float tf32_rna(float a) {
    u32 r;
    asm("cvt.rna.tf32.f32 %0, %1;" : "=r"(r) : "f"(a));
    return __uint_as_float(r);
}
__device__ __forceinline__ void cp_async16(u32 dst, const void* src) {
    asm volatile("cp.async.cg.shared.global [%0], [%1], 16;" :: "r"(dst), "l"(src));
}
#define CP_COMMIT()  asm volatile("cp.async.commit_group;")
#define CP_WAIT(n)   asm volatile("cp.async.wait_group %0;" :: "n"(n))

// m16n8k8 tf32 MMA (sm_80 baseline feature)
__device__ __forceinline__ void mma_tf32(float* c, u32 a0, u32 a1, u32 a2, u32 a3,
                                         u32 b0, u32 b1) {
    asm volatile(
        "mma.sync.aligned.m16n8k8.row.col.f32.tf32.tf32.f32 "
        "{%0,%1,%2,%3}, {%4,%5,%6,%7}, {%8,%9}, {%0,%1,%2,%3};"
        : "+f"(c[0]), "+f"(c[1]), "+f"(c[2]), "+f"(c[3])
        : "r"(a0), "r"(a1), "r"(a2), "r"(a3), "r"(b0), "r"(b1));
}

__global__ void zero_kernel() { g_flagcnt = 0; }

// ---------------------------------------------------------------------------
// FROZEN: bit-exact XLA row-sumsq (256-wide f32).
// ---------------------------------------------------------------------------
__device__ __forceinline__ float xla_row_sumsq(const float* __restrict__ row, int lane) {
    float s[4];
#pragma unroll
    for (int g = 0; g < 4; g++) {
        float x0 = row[64 * g + 2 * lane];
        float x1 = row[64 * g + 2 * lane + 1];
        s[g] = __fadd_rn(__fmul_rn(x0, x0), __fmul_rn(x1, x1));
    }
#pragma unroll
    for (int off = 16; off > 0; off >>= 1) {
#pragma unroll
        for (int g = 0; g < 4; g++)
            s[g] = __fadd_rn(s[g], __shfl_down_sync(0xffffffffu, s[g], off));
    }
    return __fadd_rn(__fadd_rn(s[0], s[2]), __fadd_rn(s[1], s[3]));
}

__global__ void norms_kernel(const float* __restrict__ x, const float* __restrict__ cb) {
    int warp = (blockIdx.x * blockDim.x + threadIdx.x) >> 5;
    int lane = threadIdx.x & 31;
    if (warp < N_ROWS) {
        float a = xla_row_sumsq(x + (size_t)warp * D_DIM, lane);
        if (lane == 0) g_xnorm[warp] = a;
    } else if (warp < N_ROWS + K_CODES) {
        int j = warp - N_ROWS;
        float b = xla_row_sumsq(cb + (size_t)j * D_DIM, lane);
        if (lane == 0) g_cnorm[j] = b;
    }
}

// ---------------------------------------------------------------------------
// tf32x3 split builders.  XA row = [hi | hi | lo], CB row = [hi | lo | hi]
// ---------------------------------------------------------------------------
__global__ void split_x_kernel(const float* __restrict__ x) {
    int i = blockIdx.x * blockDim.x + threadIdx.x;     // float4 index
    float4 v = ((const float4*)x)[i];
    float4 h, l;
    h.x = tf32_rna(v.x); l.x = tf32_rna(__fsub_rn(v.x, h.x));
    h.y = tf32_rna(v.y); l.y = tf32_rna(__fsub_rn(v.y, h.y));
    h.z = tf32_rna(v.z); l.z = tf32_rna(__fsub_rn(v.z, h.z));
    h.w = tf32_rna(v.w); l.w = tf32_rna(__fsub_rn(v.w, h.w));
    int row = i >> 6, c4 = (i & 63) << 2;
    float* base = XA + (size_t)row * K3 + c4;
    *(float4*)(base)       = h;
    *(float4*)(base + 256) = h;
    *(float4*)(base + 512) = l;
}

__global__ void split_c_kernel(const float* __restrict__ cb) {
    int i = blockIdx.x * blockDim.x + threadIdx.x;
    float4 v = ((const float4*)cb)[i];
    float4 h, l;
    h.x = tf32_rna(v.x); l.x = tf32_rna(__fsub_rn(v.x, h.x));
    h.y = tf32_rna(v.y); l.y = tf32_rna(__fsub_rn(v.y, h.y));
    h.z = tf32_rna(v.z); l.z = tf32_rna(__fsub_rn(v.z, h.z));
    h.w = tf32_rna(v.w); l.w = tf32_rna(__fsub_rn(v.w, h.w));
    int row = i >> 6, c4 = (i & 63) << 2;
    float* base = CB + (size_t)row * K3 + c4;
    *(float4*)(base)       = h;
    *(float4*)(base + 256) = l;
    *(float4*)(base + 512) = h;
}

// ---------------------------------------------------------------------------
// Main: mma.sync tf32 GEMM (256x128 per pass, K=768) + frozen quantized
// argmin with TOP-2 tracking; flags rows whose top-2 gap <= EPS_FLAG.
// 512 threads, 16 warps (8m x 2n).
// ---------------------------------------------------------------------------
#define SM_A    0
#define SM_B    (2 * BM * AST * 4)            // 73728
#define SM_CN   (SM_B + 2 * BN * BST * 4)     // 110592
#define SM_BS   (SM_CN + 512)                 // float[2][256]
#define SM_BI   (SM_BS + 2048)                // int[2][256]
#define SM_SS   (SM_BI + 2048)                // float[2][256]
#define SMEM_TOTAL (SM_SS + 2048)

__device__ __forceinline__ void load_chunk(u32 sbase, int buf, int chunk,
                                           int pass, int rowBase, int tid) {
    const float* Ag = XA + (size_t)rowBase * K3 + chunk * BK;
    const float* Bg = CB + (size_t)(pass * BN) * K3 + chunk * BK;
    u32 dA = sbase + SM_A + buf * (BM * AST * 4);
    u32 dB = sbase + SM_B + buf * (BN * BST * 4);
#pragma unroll
    for (int j = 0; j < 4; j++) {              // A: 256 rows x 32 floats
        int i = tid + j * 512;
        int row = i >> 3, c4 = (i & 7) << 2;
        cp_async16(dA + (u32)(row * AST + c4) * 4, Ag + (size_t)row * K3 + c4);
    }
#pragma unroll
    for (int j = 0; j < 2; j++) {              // B: 128 rows x 32 floats
        int i = tid + j * 512;
        int row = i >> 3, c4 = (i & 7) << 2;
        cp_async16(dB + (u32)(row * BST + c4) * 4, Bg + (size_t)row * K3 + c4);
    }
    CP_COMMIT();
}

__global__ __launch_bounds__(512, 1)
void vq_mma_kernel(void) {
    extern __shared__ char smem[];
    const u32 sbase = smem_u32(smem);
    const int tid  = threadIdx.x;
    const int lane = tid & 31;
    const int g    = lane >> 2;       // group id 0..7
    const int t    = lane & 3;        // thread-in-group
    const int wid  = tid >> 5;        // 0..15
    const int wm   = wid >> 1;        // 0..7  -> rows wm*32
    const int wn   = wid & 1;         // 0..1  -> cols wn*64
    const int rowBase = blockIdx.x * BM;

    float* sCN = (float*)(smem + SM_CN);
    float* sBS = (float*)(smem + SM_BS);
    int*   sBI = (int*)(smem + SM_BI);
    float* sSS = (float*)(smem + SM_SS);

    float ax[4];
#pragma unroll
    for (int r = 0; r < 4; r++)
        ax[r] = g_xnorm[rowBase + wm * 32 + (r >> 1) * 16 + (r & 1) * 8 + g];

    float bs[4], ss[4];
    int   bi[4];
#pragma unroll
    for (int r = 0; r < 4; r++) { bs[r] = 3.4e38f; ss[r] = 3.4e38f; bi[r] = 0; }

    for (int pass = 0; pass < PASSES; pass++) {
        if (tid < BN) sCN[tid] = g_cnorm[pass * BN + tid];

        float acc[2][8][4];
#pragma unroll
        for (int m = 0; m < 2; m++)
#pragma unroll
            for (int nt = 0; nt < 8; nt++)
#pragma unroll
                for (int e = 0; e < 4; e++) acc[m][nt][e] = 0.f;

        load_chunk(sbase, 0, 0, pass, rowBase, tid);

        for (int c = 0; c < NCHUNK; c++) {
            if (c + 1 < NCHUNK) {
                load_chunk(sbase, (c + 1) & 1, c + 1, pass, rowBase, tid);
                CP_WAIT(1);
            } else {
                CP_WAIT(0);
            }
            __syncthreads();

            const float* Ab = (const float*)(smem + SM_A + (c & 1) * (BM * AST * 4));
            const float* Bb = (const float*)(smem + SM_B + (c & 1) * (BN * BST * 4));
#pragma unroll
            for (int s = 0; s < 4; s++) {          // 4 x k8 per chunk
                u32 a[2][4];
#pragma unroll
                for (int m = 0; m < 2; m++) {
                    const float* pa = Ab + (wm * 32 + m * 16 + g) * AST + s * 8 + t;
                    a[m][0] = __float_as_uint(pa[0]);
                    a[m][1] = __float_as_uint(pa[8 * AST]);
                    a[m][2] = __float_as_uint(pa[4]);
                    a[m][3] = __float_as_uint(pa[8 * AST + 4]);
                }
#pragma unroll
                for (int nt = 0; nt < 8; nt++) {
                    const float* pb = Bb + (wn * 64 + nt * 8 + g) * BST + s * 8 + t;
                    u32 b0 = __float_as_uint(pb[0]);
                    u32 b1 = __float_as_uint(pb[4]);
                    mma_tf32(acc[0][nt], a[0][0], a[0][1], a[0][2], a[0][3], b0, b1);
                    mma_tf32(acc[1][nt], a[1][0], a[1][1], a[1][2], a[1][3], b0, b1);
                }
            }
            __syncthreads();
        }

        // ---- epilogue: FROZEN quantized score chain + top-2 running argmin
#pragma unroll
        for (int m = 0; m < 2; m++)
#pragma unroll
            for (int h = 0; h < 2; h++) {
                int r = m * 2 + h;
#pragma unroll
                for (int nt = 0; nt < 8; nt++)
#pragma unroll
                    for (int e = 0; e < 2; e++) {
                        float dot = acc[m][nt][h * 2 + e];
                        int cl = wn * 64 + nt * 8 + 2 * t + e;
                        float T  = __fadd_rn(ax[r], sCN[cl]);
                        float sc = __fsub_rn(T, __fmul_rn(2.0f, dot));
                        if (sc < bs[r]) {
                            ss[r] = bs[r]; bs[r] = sc; bi[r] = pass * BN + cl;
                        } else if (sc < ss[r]) {
                            ss[r] = sc;
                        }
                    }
            }
        __syncthreads();
    }

    // ---- cross-lane top-2 merge within 4-lane group
#pragma unroll
    for (int q = 1; q <= 2; q <<= 1) {
#pragma unroll
        for (int r = 0; r < 4; r++) {
            float ob = __shfl_xor_sync(0xffffffffu, bs[r], q);
            int   oi = __shfl_xor_sync(0xffffffffu, bi[r], q);
            float os = __shfl_xor_sync(0xffffffffu, ss[r], q);
            if (ob < bs[r] || (ob == bs[r] && oi < bi[r])) {
                ss[r] = fminf(os, bs[r]); bs[r] = ob; bi[r] = oi;
            } else {
                ss[r] = fminf(ss[r], ob);
            }
        }
    }
    if (t == 0) {
#pragma unroll
        for (int r = 0; r < 4; r++) {
            int row = wm * 32 + (r >> 1) * 16 + (r & 1) * 8 + g;
            sBS[wn * 256 + row] = bs[r];
            sBI[wn * 256 + row] = bi[r];
            sSS[wn * 256 + row] = ss[r];
        }
    }
    __syncthreads();
    if (tid < BM) {
        float b0 = sBS[tid], b1 = sBS[256 + tid];
        int   i0 = sBI[tid], i1 = sBI[256 + tid];
        float s0 = sSS[tid], s1 = sSS[256 + tid];
        float nb, ns; int ni;
        if (b1 < b0 || (b1 == b0 && i1 < i0)) { nb = b1; ni = i1; ns = fminf(s1, b0); }
        else                                  { nb = b0; ni = i0; ns = fminf(s0, b1); }
        g_widx[rowBase + tid] = ni;
        if (__fsub_rn(ns, nb) <= EPS_FLAG) {
            int slot = atomicAdd(&g_flagcnt, 1);
            g_flaglist[slot] = rowBase + tid;
        }
    }
}

// ---------------------------------------------------------------------------
// Rescue: exact fp32 re-scan (R5 sequential-k fmaf chain + frozen quantized
// score) over ALL 2048 codes for each flagged row. 8 rows per block batch.
// ---------------------------------------------------------------------------
__global__ __launch_bounds__(256, 2)
void rescue_kernel(const float* __restrict__ x, const float* __restrict__ cb) {
    __shared__ int   srows[8];
    __shared__ float sx[8][256];
    __shared__ float rv[256];
    __shared__ int   ri[256];

    const int tid = threadIdx.x;
    const int cnt = g_flagcnt;

    for (int base = blockIdx.x * 8; base < cnt; base += gridDim.x * 8) {
        if (tid < 8)
            srows[tid] = (base + tid < cnt) ? g_flaglist[base + tid] : g_flaglist[base];
        __syncthreads();
#pragma unroll 1
        for (int i = tid; i < 8 * 256; i += 256) {
            int rr = i >> 8, k = i & 255;
            sx[rr][k] = x[(size_t)srows[rr] * D_DIM + k];
        }
        __syncthreads();

        // 64 accumulators: 8 codes (tid + 256*jc) x 8 rows; sequential-k fmaf
        float acc[8][8];
#pragma unroll
        for (int jc = 0; jc < 8; jc++)
#pragma unroll
            for (int rr = 0; rr < 8; rr++) acc[jc][rr] = 0.f;

#pragma unroll 1
        for (int k4 = 0; k4 < 64; k4++) {
            float4 cv[8];
#pragma unroll
            for (int jc = 0; jc < 8; jc++)
                cv[jc] = *(const float4*)(cb + (size_t)(jc * 256 + tid) * D_DIM + k4 * 4);
#pragma unroll
            for (int rr = 0; rr < 8; rr++) {
                float x0 = sx[rr][k4 * 4 + 0];
                float x1 = sx[rr][k4 * 4 + 1];
                float x2 = sx[rr][k4 * 4 + 2];
                float x3 = sx[rr][k4 * 4 + 3];
#pragma unroll
                for (int jc = 0; jc < 8; jc++) {
                    float a = acc[jc][rr];
                    a = fmaf(x0, cv[jc].x, a);
                    a = fmaf(x1, cv[jc].y, a);
                    a = fmaf(x2, cv[jc].z, a);
                    a = fmaf(x3, cv[jc].w, a);
                    acc[jc][rr] = a;
                }
            }
        }

        // per-row argmin over this thread's 8 codes (ascending jc = ascending
        // code index), then block tree with (value, index) comparator.
#pragma unroll 1
        for (int rr = 0; rr < 8; rr++) {
            int   grow = srows[rr];
            float an   = g_xnorm[grow];
            float lb = 3.4e38f;
            int   li = 0;
#pragma unroll
            for (int jc = 0; jc < 8; jc++) {
                int code = jc * 256 + tid;
                float T  = __fadd_rn(an, g_cnorm[code]);
                float sc = __fsub_rn(T, __fmul_rn(2.0f, acc[jc][rr]));
                if (sc < lb) { lb = sc; li = code; }
            }
            rv[tid] = lb; ri[tid] = li;
            __syncthreads();
#pragma unroll
            for (int s = 128; s > 0; s >>= 1) {
                if (tid < s) {
                    float ov = rv[tid + s]; int oi = ri[tid + s];
                    if (ov < rv[tid] || (ov == rv[tid] && oi < ri[tid])) {
                        rv[tid] = ov; ri[tid] = oi;
                    }
                }
                __syncthreads();
            }
            if (tid == 0 && base + rr < cnt) g_widx[grow] = ri[0];
            __syncthreads();
        }
        __syncthreads();
    }
}

// ---------------------------------------------------------------------------
// Gather + output (frozen rounding) + loss partials. 256 blocks x 128 rows.
// ---------------------------------------------------------------------------
__global__ __launch_bounds__(256, 2)
void gather_kernel(const float* __restrict__ x, const float* __restrict__ cb,
                   float* __restrict__ out) {
    __shared__ int   sw[128];
    __shared__ float sred[256];
    const int tid = threadIdx.x;
    const int rowBase = blockIdx.x * 128;

    if (tid < 128) sw[tid] = g_widx[rowBase + tid];
    __syncthreads();

    float lsum = 0.f;
#pragma unroll 1
    for (int i = tid; i < 128 * (D_DIM / 4); i += 256) {
        int row = i >> 6;
        int c4  = (i & 63) << 2;
        size_t goff = (size_t)(rowBase + row) * D_DIM + c4;
        float4 xv = *(const float4*)(x + goff);
        float4 cv = *(const float4*)(cb + (size_t)sw[row] * D_DIM + c4);
        float4 o;
        o.x = __fadd_rn(xv.x, __fsub_rn(cv.x, xv.x));
        o.y = __fadd_rn(xv.y, __fsub_rn(cv.y, xv.y));
        o.z = __fadd_rn(xv.z, __fsub_rn(cv.z, xv.z));
        o.w = __fadd_rn(xv.w, __fsub_rn(cv.w, xv.w));
        *(float4*)(out + goff) = o;
        float dx = __fsub_rn(xv.x, cv.x); lsum = fmaf(dx, dx, lsum);
        float dy = __fsub_rn(xv.y, cv.y); lsum = fmaf(dy, dy, lsum);
        float dz = __fsub_rn(xv.z, cv.z); lsum = fmaf(dz, dz, lsum);
        float dw = __fsub_rn(xv.w, cv.w); lsum = fmaf(dw, dw, lsum);
    }
    __syncthreads();
    sred[tid] = lsum;
    __syncthreads();
#pragma unroll
    for (int s = 128; s > 0; s >>= 1) {
        if (tid < s) sred[tid] += sred[tid + s];
        __syncthreads();
    }
    if (tid == 0) g_partial[blockIdx.x] = sred[0];
}

// ---------------------------------------------------------------------------
// Deterministic loss finalize. loss = 1.25 * mean((x-c)^2).
// ---------------------------------------------------------------------------
__global__ void loss_kernel(float* __restrict__ out, int out_size) {
    __shared__ double sd[256];
    int tid = threadIdx.x;
    sd[tid] = (double)g_partial[tid];
    __syncthreads();
#pragma unroll
    for (int s = 128; s > 0; s >>= 1) {
        if (tid < s) sd[tid] += sd[tid + s];
        __syncthreads();
    }
    if (tid == 0) {
        double mean = sd[0] / (double)((size_t)N_ROWS * D_DIM);
        out[out_size - 1] = (float)(1.25 * mean);
    }
}

// ---------------------------------------------------------------------------
extern "C" void kernel_launch(void* const* d_in, const int* in_sizes, int n_in,
                              void* d_out, int out_size) {
    const float* x  = (const float*)d_in[0];   // [N, D]
    const float* cb = (const float*)d_in[1];   // [K, D]
    float* out = (float*)d_out;                // [N*D] quantized + [1] loss

    (void)in_sizes; (void)n_in;

    cudaFuncSetAttribute(vq_mma_kernel, cudaFuncAttributeMaxDynamicSharedMemorySize,
                         SMEM_TOTAL);

    zero_kernel<<<1, 1>>>();
    norms_kernel<<<(N_ROWS + K_CODES) / 8, 256>>>(x, cb);
    split_x_kernel<<<(N_ROWS * D_DIM / 4) / 256, 256>>>(x);
    split_c_kernel<<<(K_CODES * D_DIM / 4) / 256, 256>>>(cb);
    vq_mma_kernel<<<NBLK, 512, SMEM_TOTAL>>>();
    rescue_kernel<<<256, 256>>>(x, cb);
    gather_kernel<<<GBLK, 256>>>(x, cb, out);
    loss_kernel<<<1, 256>>>(out, out_size);
}